// round 1
// baseline (speedup 1.0000x reference)
#include <cuda_runtime.h>
#include <math.h>

#define SQ   64
#define BA   64
#define HID  1024
#define EMBD 1024
#define VOC  10000
#define BH   (BA*HID)
#define MROWS (SQ*BA)   // 4096

// Scratch (device globals: no allocation allowed)
__device__ float g_P0[MROWS*HID];
__device__ float g_H0[MROWS*HID];
__device__ float g_P1[MROWS*HID];
__device__ float g_H1[MROWS*HID];

// C[M,N] = A[M,K] @ B[N,K]^T (+ bias). A rows optionally gathered via idx.
// Block tile 128x128, K-tile 16, 256 threads, 8x8 microtile.
template<bool GATHER, bool BIAS>
__global__ __launch_bounds__(256, 2)
void gemm_tn(const float* __restrict__ A, const float* __restrict__ Bm,
             const float* __restrict__ bias, const int* __restrict__ idx,
             float* __restrict__ C, int N, int K)
{
    __shared__ float As[16][132];
    __shared__ float Bs[16][132];
    const int t = threadIdx.x;
    const int mBase = blockIdx.y * 128;
    const int nBase = blockIdx.x * 128;

    const int lr  = t >> 2;         // 0..63
    const int lc4 = (t & 3) * 4;    // 0,4,8,12

    float acc[8][8];
    #pragma unroll
    for (int i = 0; i < 8; i++)
        #pragma unroll
        for (int j = 0; j < 8; j++) acc[i][j] = 0.f;

    const int m0 = (t >> 4) * 8;
    const int n0 = (t & 15) * 8;

    for (int kt = 0; kt < K; kt += 16) {
        // stage A tile (transposed into As[k][m])
        #pragma unroll
        for (int i = 0; i < 2; i++) {
            int r  = lr + i * 64;
            int gm = mBase + r;
            const float* arow = GATHER ? (A + (size_t)idx[gm] * K)
                                       : (A + (size_t)gm * K);
            float4 v = *(const float4*)(arow + kt + lc4);
            As[lc4 + 0][r] = v.x; As[lc4 + 1][r] = v.y;
            As[lc4 + 2][r] = v.z; As[lc4 + 3][r] = v.w;
        }
        // stage B tile (transposed into Bs[k][n]); guard N boundary
        #pragma unroll
        for (int i = 0; i < 2; i++) {
            int r  = lr + i * 64;
            int gn = nBase + r;
            float4 v = make_float4(0.f, 0.f, 0.f, 0.f);
            if (gn < N) v = *(const float4*)(Bm + (size_t)gn * K + kt + lc4);
            Bs[lc4 + 0][r] = v.x; Bs[lc4 + 1][r] = v.y;
            Bs[lc4 + 2][r] = v.z; Bs[lc4 + 3][r] = v.w;
        }
        __syncthreads();

        #pragma unroll
        for (int kk = 0; kk < 16; kk++) {
            float a[8], b[8];
            #pragma unroll
            for (int i = 0; i < 8; i++) a[i] = As[kk][m0 + i];
            #pragma unroll
            for (int j = 0; j < 8; j++) b[j] = Bs[kk][n0 + j];
            #pragma unroll
            for (int i = 0; i < 8; i++)
                #pragma unroll
                for (int j = 0; j < 8; j++) acc[i][j] += a[i] * b[j];
        }
        __syncthreads();
    }

    #pragma unroll
    for (int i = 0; i < 8; i++) {
        int m = mBase + m0 + i;
        #pragma unroll
        for (int j = 0; j < 8; j++) {
            int n = nBase + n0 + j;
            if (n < N)
                C[(size_t)m * N + n] = acc[i][j] + (BIAS ? bias[n] : 0.f);
        }
    }
}

// One recurrence step: out[b][hb+h] = tanh(P[b][hb+h] + sum_k Hprev[b][k]*W[hb+h][k] + bias[hb+h])
// grid = 64 CTAs (16 h-columns each), 256 threads, each thread does 4 batch rows.
__global__ __launch_bounds__(256)
void rnn_step(const float* __restrict__ Hprev, const float* __restrict__ W,
              const float* __restrict__ P, const float* __restrict__ bias,
              float* __restrict__ out)
{
    __shared__ float As[64][68];   // [k? no: b][k-tile], padded: conflict-free
    __shared__ float Ws[16][66];
    const int t  = threadIdx.x;
    const int hb = blockIdx.x * 16;
    const int h  = t & 15;   // output column within tile
    const int b0 = t >> 4;   // 0..15 (rows b0, b0+16, b0+32, b0+48)
    const int c  = t & 15;   // float4 column for staging
    const int rr = t >> 4;   // staging row

    float acc0 = 0.f, acc1 = 0.f, acc2 = 0.f, acc3 = 0.f;

    for (int kt = 0; kt < HID; kt += 64) {
        #pragma unroll
        for (int i = 0; i < 4; i++) {
            int r = rr + i * 16;
            float4 v = *(const float4*)(Hprev + (size_t)r * HID + kt + 4 * c);
            *(float4*)&As[r][4 * c] = v;
        }
        {
            float4 v = *(const float4*)(W + (size_t)(hb + rr) * HID + kt + 4 * c);
            Ws[rr][4 * c + 0] = v.x; Ws[rr][4 * c + 1] = v.y;
            Ws[rr][4 * c + 2] = v.z; Ws[rr][4 * c + 3] = v.w;
        }
        __syncthreads();

        #pragma unroll
        for (int k = 0; k < 64; k++) {
            float w = Ws[h][k];
            acc0 += As[b0     ][k] * w;
            acc1 += As[b0 + 16][k] * w;
            acc2 += As[b0 + 32][k] * w;
            acc3 += As[b0 + 48][k] * w;
        }
        __syncthreads();
    }

    float bb = bias[hb + h];
    out[(size_t)(b0     ) * HID + hb + h] = tanhf(acc0 + P[(size_t)(b0     ) * HID + hb + h] + bb);
    out[(size_t)(b0 + 16) * HID + hb + h] = tanhf(acc1 + P[(size_t)(b0 + 16) * HID + hb + h] + bb);
    out[(size_t)(b0 + 32) * HID + hb + h] = tanhf(acc2 + P[(size_t)(b0 + 32) * HID + hb + h] + bb);
    out[(size_t)(b0 + 48) * HID + hb + h] = tanhf(acc3 + P[(size_t)(b0 + 48) * HID + hb + h] + bb);
}

__global__ void write_hidden(const float* __restrict__ h0, const float* __restrict__ h1,
                             float* __restrict__ dst)
{
    int i = blockIdx.x * 256 + threadIdx.x;
    if (i < BH) {
        dst[i]      = h0[i];
        dst[BH + i] = h1[i];
    }
}

extern "C" void kernel_launch(void* const* d_in, const int* in_sizes, int n_in,
                              void* d_out, int out_size)
{
    const int*   inputs = (const int*)  d_in[0];
    const float* hidden = (const float*)d_in[1];
    const float* emb    = (const float*)d_in[2];
    const float* W0     = (const float*)d_in[3];
    const float* Wh0    = (const float*)d_in[4];
    const float* b0     = (const float*)d_in[5];
    const float* W1     = (const float*)d_in[6];
    const float* Wh1    = (const float*)d_in[7];
    const float* b1     = (const float*)d_in[8];
    const float* Wd     = (const float*)d_in[9];
    const float* bd     = (const float*)d_in[10];
    float* out = (float*)d_out;

    float *P0, *H0, *P1, *H1;
    cudaGetSymbolAddress((void**)&P0, g_P0);
    cudaGetSymbolAddress((void**)&H0, g_H0);
    cudaGetSymbolAddress((void**)&P1, g_P1);
    cudaGetSymbolAddress((void**)&H1, g_H1);

    // K1: P0 = emb[inputs] @ W0^T   [4096,1024]x[1024,1024]
    gemm_tn<true, false><<<dim3(HID / 128, MROWS / 128), 256>>>(
        emb, W0, nullptr, inputs, P0, HID, EMBD);

    // Layer 0 recurrence (sequential)
    for (int tt = 0; tt < SQ; tt++) {
        const float* hp = (tt == 0) ? hidden : (H0 + (size_t)(tt - 1) * BH);
        rnn_step<<<64, 256>>>(hp, Wh0, P0 + (size_t)tt * BH, b0, H0 + (size_t)tt * BH);
    }

    // K3: P1 = H0_all @ W1^T
    gemm_tn<false, false><<<dim3(HID / 128, MROWS / 128), 256>>>(
        H0, W1, nullptr, nullptr, P1, HID, HID);

    // Layer 1 recurrence (sequential)
    for (int tt = 0; tt < SQ; tt++) {
        const float* hp = (tt == 0) ? (hidden + BH) : (H1 + (size_t)(tt - 1) * BH);
        rnn_step<<<64, 256>>>(hp, Wh1, P1 + (size_t)tt * BH, b1, H1 + (size_t)tt * BH);
    }

    // K5: logits = H1_all @ Wd^T + bd   [4096,1024]x[1024,10000]
    gemm_tn<false, true><<<dim3((VOC + 127) / 128, MROWS / 128), 256>>>(
        H1, Wd, bd, nullptr, out, VOC, HID);

    // hidden_final = [h0_last, h1_last]
    if (out_size >= MROWS * VOC + 2 * BH)
        write_hidden<<<(BH + 255) / 256, 256>>>(
            H0 + (size_t)(SQ - 1) * BH, H1 + (size_t)(SQ - 1) * BH,
            out + (size_t)MROWS * VOC);
}

// round 2
// speedup vs baseline: 1.5083x; 1.5083x over previous
#include <cuda_runtime.h>
#include <math.h>

#define SQ   64
#define BA   64
#define HID  1024
#define EMBD 1024
#define VOC  10000
#define BH   (BA*HID)
#define MROWS (SQ*BA)   // 4096

#define NCTA 128
#define KSLICES 8
#define KS  128        // k elements per slice
#define NC  64         // output columns per CTA

// Scratch (device globals: no allocation allowed)
__device__ float g_P0[MROWS*HID];
__device__ float g_H0[MROWS*HID];
__device__ float g_P1[MROWS*HID];
__device__ float g_H1[MROWS*HID];
__device__ float g_part[KSLICES*BA*HID];   // 2 MB split-K partials

__device__ volatile unsigned g_gen;
__device__ unsigned g_cnt;

__device__ __forceinline__ void gbar()
{
    __syncthreads();
    if (threadIdx.x == 0) {
        __threadfence();
        unsigned my = g_gen;
        unsigned a = atomicAdd(&g_cnt, 1);
        if (a == NCTA - 1) {
            atomicExch(&g_cnt, 0);
            __threadfence();
            g_gen = my + 1;
        } else {
            while (g_gen == my) { }
        }
        __threadfence();
    }
    __syncthreads();
}

// ---------------------------------------------------------------------------
// Persistent recurrence kernel: runs all SQ steps of one layer.
// Hout[t] = tanh(P[t] + Hprev @ W^T + bias), Hprev = Hout[t-1] (or Hinit).
// 128 CTAs = 8 k-slices x 16 col-groups. W slice cached in smem once.
// ---------------------------------------------------------------------------
__global__ __launch_bounds__(256, 1)
void rnn_layer_persist(const float* __restrict__ Hinit,
                       const float* __restrict__ W,
                       const float* __restrict__ P,
                       const float* __restrict__ bias,
                       float* __restrict__ Hout)
{
    extern __shared__ float sm[];
    float* Ws = sm;                 // [KS][68]  (k-major, padded)
    float* Hs = sm + KS * 68;       // [BA][132] (b-major, padded)

    const int t  = threadIdx.x;
    const int ks = blockIdx.x & 7;
    const int cg = blockIdx.x >> 3;

    // Load W slice once: Ws[kk][c] = W[cg*NC + c][ks*KS + kk]
    #pragma unroll
    for (int i = 0; i < 8; i++) {
        int idx = t + i * 256;          // 2048 float4 = 64 rows x 32
        int c   = idx >> 5;
        int f   = idx & 31;
        float4 v = *(const float4*)(W + (size_t)(cg * NC + c) * HID + ks * KS + 4 * f);
        Ws[(4 * f + 0) * 68 + c] = v.x;
        Ws[(4 * f + 1) * 68 + c] = v.y;
        Ws[(4 * f + 2) * 68 + c] = v.z;
        Ws[(4 * f + 3) * 68 + c] = v.w;
    }

    const int tx = t & 15, ty = t >> 4;
    const int c0 = tx * 4, b0 = ty * 4;

    for (int step = 0; step < SQ; step++) {
        const float* Hprev = (step == 0) ? Hinit : (Hout + (size_t)(step - 1) * BH);

        // Stage Hs[b][kk] = Hprev[b][ks*KS + kk]
        #pragma unroll
        for (int i = 0; i < 8; i++) {
            int idx = t + i * 256;
            int b = idx >> 5, f = idx & 31;
            float4 v = *(const float4*)(Hprev + (size_t)b * HID + ks * KS + 4 * f);
            *(float4*)(Hs + b * 132 + 4 * f) = v;
        }
        __syncthreads();

        float acc[4][4];
        #pragma unroll
        for (int i = 0; i < 4; i++)
            #pragma unroll
            for (int j = 0; j < 4; j++) acc[i][j] = 0.f;

        #pragma unroll 4
        for (int kk = 0; kk < KS; kk += 4) {
            float4 wv[4], hv[4];
            #pragma unroll
            for (int u = 0; u < 4; u++) wv[u] = *(const float4*)(Ws + (kk + u) * 68 + c0);
            #pragma unroll
            for (int i = 0; i < 4; i++) hv[i] = *(const float4*)(Hs + (b0 + i) * 132 + kk);
            #pragma unroll
            for (int i = 0; i < 4; i++) {
                const float h0v = hv[i].x, h1v = hv[i].y, h2v = hv[i].z, h3v = hv[i].w;
                #pragma unroll
                for (int j = 0; j < 4; j++) {
                    float* a = &acc[i][j];
                    const float* w0 = &((const float*)&wv[0])[j];
                    const float* w1 = &((const float*)&wv[1])[j];
                    const float* w2 = &((const float*)&wv[2])[j];
                    const float* w3 = &((const float*)&wv[3])[j];
                    *a += h0v * *w0;
                    *a += h1v * *w1;
                    *a += h2v * *w2;
                    *a += h3v * *w3;
                }
            }
        }

        // Write partials: g_part[ks][b][global col]
        float* pp = g_part + (size_t)ks * BA * HID + (size_t)cg * NC;
        #pragma unroll
        for (int i = 0; i < 4; i++) {
            float4 v = make_float4(acc[i][0], acc[i][1], acc[i][2], acc[i][3]);
            *(float4*)(pp + (size_t)(b0 + i) * HID + c0) = v;
        }
        __threadfence();
        gbar();

        // Reduce: each CTA finalizes 512 outputs (coalesced)
        const float* Pt = P + (size_t)step * BH;
        float*       Ht = Hout + (size_t)step * BH;
        int base = blockIdx.x * 512;
        #pragma unroll
        for (int r = 0; r < 2; r++) {
            int o = base + r * 256 + t;
            int c = o & (HID - 1);
            float s = 0.f;
            #pragma unroll
            for (int k2 = 0; k2 < KSLICES; k2++)
                s += g_part[(size_t)k2 * BA * HID + o];
            Ht[o] = tanhf(s + Pt[o] + bias[c]);
        }
        __threadfence();
        gbar();
    }
}

// ---------------------------------------------------------------------------
// Big GEMM: C[M,N] = A[M,K] @ B[N,K]^T (+ bias). A rows optionally gathered.
// ---------------------------------------------------------------------------
template<bool GATHER, bool BIAS>
__global__ __launch_bounds__(256, 2)
void gemm_tn(const float* __restrict__ A, const float* __restrict__ Bm,
             const float* __restrict__ bias, const int* __restrict__ idx,
             float* __restrict__ C, int N, int K)
{
    __shared__ float As[16][132];
    __shared__ float Bs[16][132];
    const int t = threadIdx.x;
    const int mBase = blockIdx.y * 128;
    const int nBase = blockIdx.x * 128;

    const int lr  = t >> 2;
    const int lc4 = (t & 3) * 4;

    float acc[8][8];
    #pragma unroll
    for (int i = 0; i < 8; i++)
        #pragma unroll
        for (int j = 0; j < 8; j++) acc[i][j] = 0.f;

    const int m0 = (t >> 4) * 8;
    const int n0 = (t & 15) * 8;

    for (int kt = 0; kt < K; kt += 16) {
        #pragma unroll
        for (int i = 0; i < 2; i++) {
            int r  = lr + i * 64;
            int gm = mBase + r;
            const float* arow = GATHER ? (A + (size_t)idx[gm] * K)
                                       : (A + (size_t)gm * K);
            float4 v = *(const float4*)(arow + kt + lc4);
            As[lc4 + 0][r] = v.x; As[lc4 + 1][r] = v.y;
            As[lc4 + 2][r] = v.z; As[lc4 + 3][r] = v.w;
        }
        #pragma unroll
        for (int i = 0; i < 2; i++) {
            int r  = lr + i * 64;
            int gn = nBase + r;
            float4 v = make_float4(0.f, 0.f, 0.f, 0.f);
            if (gn < N) v = *(const float4*)(Bm + (size_t)gn * K + kt + lc4);
            Bs[lc4 + 0][r] = v.x; Bs[lc4 + 1][r] = v.y;
            Bs[lc4 + 2][r] = v.z; Bs[lc4 + 3][r] = v.w;
        }
        __syncthreads();

        #pragma unroll
        for (int kk = 0; kk < 16; kk++) {
            float a[8], b[8];
            #pragma unroll
            for (int i = 0; i < 8; i++) a[i] = As[kk][m0 + i];
            #pragma unroll
            for (int j = 0; j < 8; j++) b[j] = Bs[kk][n0 + j];
            #pragma unroll
            for (int i = 0; i < 8; i++)
                #pragma unroll
                for (int j = 0; j < 8; j++) acc[i][j] += a[i] * b[j];
        }
        __syncthreads();
    }

    #pragma unroll
    for (int i = 0; i < 8; i++) {
        int m = mBase + m0 + i;
        #pragma unroll
        for (int j = 0; j < 8; j++) {
            int n = nBase + n0 + j;
            if (n < N)
                C[(size_t)m * N + n] = acc[i][j] + (BIAS ? bias[n] : 0.f);
        }
    }
}

__global__ void write_hidden(const float* __restrict__ h0, const float* __restrict__ h1,
                             float* __restrict__ dst)
{
    int i = blockIdx.x * 256 + threadIdx.x;
    if (i < BH) {
        dst[i]      = h0[i];
        dst[BH + i] = h1[i];
    }
}

extern "C" void kernel_launch(void* const* d_in, const int* in_sizes, int n_in,
                              void* d_out, int out_size)
{
    const int*   inputs = (const int*)  d_in[0];
    const float* hidden = (const float*)d_in[1];
    const float* emb    = (const float*)d_in[2];
    const float* W0     = (const float*)d_in[3];
    const float* Wh0    = (const float*)d_in[4];
    const float* b0     = (const float*)d_in[5];
    const float* W1     = (const float*)d_in[6];
    const float* Wh1    = (const float*)d_in[7];
    const float* b1     = (const float*)d_in[8];
    const float* Wd     = (const float*)d_in[9];
    const float* bd     = (const float*)d_in[10];
    float* out = (float*)d_out;

    float *P0, *H0, *P1, *H1;
    cudaGetSymbolAddress((void**)&P0, g_P0);
    cudaGetSymbolAddress((void**)&H0, g_H0);
    cudaGetSymbolAddress((void**)&P1, g_P1);
    cudaGetSymbolAddress((void**)&H1, g_H1);

    static bool attr_set = false;
    const int smem_bytes = (KS * 68 + BA * 132) * 4;   // 68608
    if (!attr_set) {
        cudaFuncSetAttribute(rnn_layer_persist,
                             cudaFuncAttributeMaxDynamicSharedMemorySize, smem_bytes);
        attr_set = true;
    }

    // K1: P0 = emb[inputs] @ W0^T
    gemm_tn<true, false><<<dim3(HID / 128, MROWS / 128), 256>>>(
        emb, W0, nullptr, inputs, P0, HID, EMBD);

    // Layer 0 recurrence (one persistent kernel, all 64 steps)
    rnn_layer_persist<<<NCTA, 256, smem_bytes>>>(hidden, Wh0, P0, b0, H0);

    // K3: P1 = H0_all @ W1^T
    gemm_tn<false, false><<<dim3(HID / 128, MROWS / 128), 256>>>(
        H0, W1, nullptr, nullptr, P1, HID, HID);

    // Layer 1 recurrence
    rnn_layer_persist<<<NCTA, 256, smem_bytes>>>(hidden + BH, Wh1, P1, b1, H1);

    // K5: logits = H1_all @ Wd^T + bd
    gemm_tn<false, true><<<dim3((VOC + 127) / 128, MROWS / 128), 256>>>(
        H1, Wd, bd, nullptr, out, VOC, HID);

    // hidden_final
    if (out_size >= MROWS * VOC + 2 * BH)
        write_hidden<<<(BH + 255) / 256, 256>>>(
            H0 + (size_t)(SQ - 1) * BH, H1 + (size_t)(SQ - 1) * BH,
            out + (size_t)MROWS * VOC);
}

// round 7
// speedup vs baseline: 2.0148x; 1.3358x over previous
#include <cuda_runtime.h>
#include <cuda_bf16.h>
#include <stdint.h>
#include <math.h>

#define SQ   64
#define BA   64
#define HID  1024
#define EMBD 1024
#define VOC  10000
#define BH   (BA*HID)
#define MROWS (SQ*BA)   // 4096
#define K3   (3*HID)    // 3072 split-bf16 K

#define NCTA 128
#define KSLICES 8
#define KS  128
#define NC  64

// ---- scratch (device globals) ----
__device__ float g_P0[MROWS*HID];
__device__ float g_H0[MROWS*HID];
__device__ float g_P1[MROWS*HID];
__device__ float g_H1[MROWS*HID];
__device__ float g_part[KSLICES*BA*HID];

__device__ __nv_bfloat16 g_A3 [MROWS*K3];     // packed A (hi|hi|lo)
__device__ __nv_bfloat16 g_W03[HID*K3];       // packed B (hi|lo|hi)
__device__ __nv_bfloat16 g_W13[HID*K3];
__device__ __nv_bfloat16 g_Wd3[VOC*K3];

__device__ volatile unsigned g_gen;
__device__ unsigned g_cnt;

__device__ __forceinline__ void gbar()
{
    __syncthreads();
    if (threadIdx.x == 0) {
        __threadfence();
        unsigned my = g_gen;
        unsigned a = atomicAdd(&g_cnt, 1);
        if (a == NCTA - 1) {
            atomicExch(&g_cnt, 0);
            __threadfence();
            g_gen = my + 1;
        } else {
            while (g_gen == my) { }
        }
        __threadfence();
    }
    __syncthreads();
}

// ---------------------------------------------------------------------------
// Split-pack: fp32 [R,HID] -> bf16 [R,3*HID].
// A-order (AORD=1): [hi|hi|lo].  B-order (AORD=0): [hi|lo|hi].
// ---------------------------------------------------------------------------
template<bool GATHER, bool AORD>
__global__ __launch_bounds__(256)
void pack_split(const float* __restrict__ src, const int* __restrict__ idx,
                __nv_bfloat16* __restrict__ dst, int R)
{
    long i = (long)blockIdx.x * 256 + threadIdx.x;     // over R*HID/4
    if (i >= (long)R * (HID / 4)) return;
    int r  = (int)(i / (HID / 4));
    int k4 = (int)(i % (HID / 4)) * 4;
    const float* row = GATHER ? (src + (size_t)idx[r] * HID)
                              : (src + (size_t)r * HID);
    float4 v = *(const float4*)(row + k4);

    __nv_bfloat16 h[4], l[4];
    float f[4] = {v.x, v.y, v.z, v.w};
    #pragma unroll
    for (int j = 0; j < 4; j++) {
        h[j] = __float2bfloat16(f[j]);
        l[j] = __float2bfloat16(f[j] - __bfloat162float(h[j]));
    }
    __nv_bfloat16* d = dst + (size_t)r * K3;
    *(uint2*)(d + k4)                           = *(uint2*)h;            // seg0: hi
    *(uint2*)(d + (AORD ? HID : 2*HID) + k4)    = *(uint2*)h;            // hi
    *(uint2*)(d + (AORD ? 2*HID : HID) + k4)    = *(uint2*)l;            // lo
}

// ---------------------------------------------------------------------------
// bf16 tensor-core GEMM: C[M,N] = A[M,K3] @ B[N,K3]^T (+bias), fp32 accum.
// CTA 128x128, K-tile 32, 256 threads (8 warps: 4m x 2n), mma.m16n8k16.
// grid.x = M/128 (fast), grid.y = N tiles.
// ---------------------------------------------------------------------------
#define SMP 40   // padded row stride in halves

__device__ __forceinline__ void mma16816(float* c, const uint32_t* a, const uint32_t* b)
{
    asm volatile(
        "mma.sync.aligned.m16n8k16.row.col.f32.bf16.bf16.f32 "
        "{%0,%1,%2,%3}, {%4,%5,%6,%7}, {%8,%9}, {%0,%1,%2,%3};"
        : "+f"(c[0]), "+f"(c[1]), "+f"(c[2]), "+f"(c[3])
        : "r"(a[0]), "r"(a[1]), "r"(a[2]), "r"(a[3]), "r"(b[0]), "r"(b[1]));
}

template<bool BIAS, bool GUARD>
__global__ __launch_bounds__(256, 2)
void gemm_bf16(const __nv_bfloat16* __restrict__ A, const __nv_bfloat16* __restrict__ B,
               const float* __restrict__ bias, float* __restrict__ C, int N)
{
    __shared__ __nv_bfloat16 As[2][128 * SMP];
    __shared__ __nv_bfloat16 Bs[2][128 * SMP];

    const int t    = threadIdx.x;
    const int warp = t >> 5, lane = t & 31;
    const int mBase = blockIdx.x * 128;
    const int nBase = blockIdx.y * 128;
    const int warpM = (warp >> 1) * 32;
    const int warpN = (warp & 1) * 64;

    const int lr = t >> 1;            // staging row 0..127
    const int lk = (t & 1) * 16;      // 0 / 16

    const __nv_bfloat16* Ag = A + (size_t)(mBase + lr) * K3 + lk;
    int gn = nBase + lr;
    bool bvalid = true;
    if (GUARD && gn >= N) { bvalid = false; gn = N - 1; }
    const __nv_bfloat16* Bg = B + (size_t)gn * K3 + lk;

    uint4 av0 = *(const uint4*)(Ag);
    uint4 av1 = *(const uint4*)(Ag + 8);
    uint4 bv0 = make_uint4(0,0,0,0), bv1 = make_uint4(0,0,0,0);
    if (!GUARD || bvalid) { bv0 = *(const uint4*)(Bg); bv1 = *(const uint4*)(Bg + 8); }

    float acc[2][8][4];
    #pragma unroll
    for (int mi = 0; mi < 2; mi++)
        #pragma unroll
        for (int ni = 0; ni < 8; ni++)
            #pragma unroll
            for (int j = 0; j < 4; j++) acc[mi][ni][j] = 0.f;

    int buf = 0;
    for (int kt = 0; kt < K3; kt += 32) {
        // stage current tile
        *(uint4*)&As[buf][lr * SMP + lk]     = av0;
        *(uint4*)&As[buf][lr * SMP + lk + 8] = av1;
        *(uint4*)&Bs[buf][lr * SMP + lk]     = bv0;
        *(uint4*)&Bs[buf][lr * SMP + lk + 8] = bv1;
        __syncthreads();

        // prefetch next
        if (kt + 32 < K3) {
            av0 = *(const uint4*)(Ag + kt + 32);
            av1 = *(const uint4*)(Ag + kt + 40);
            if (!GUARD || bvalid) {
                bv0 = *(const uint4*)(Bg + kt + 32);
                bv1 = *(const uint4*)(Bg + kt + 40);
            }
        }

        // compute 2 x k16
        #pragma unroll
        for (int ks = 0; ks < 2; ks++) {
            const int kk = ks * 16 + (lane & 3) * 2;
            uint32_t a[2][4], b[8][2];
            #pragma unroll
            for (int mi = 0; mi < 2; mi++) {
                int r0 = warpM + mi * 16 + (lane >> 2);
                a[mi][0] = *(const uint32_t*)&As[buf][ r0      * SMP + kk];
                a[mi][1] = *(const uint32_t*)&As[buf][(r0 + 8) * SMP + kk];
                a[mi][2] = *(const uint32_t*)&As[buf][ r0      * SMP + kk + 8];
                a[mi][3] = *(const uint32_t*)&As[buf][(r0 + 8) * SMP + kk + 8];
            }
            #pragma unroll
            for (int ni = 0; ni < 8; ni++) {
                int n0 = warpN + ni * 8 + (lane >> 2);
                b[ni][0] = *(const uint32_t*)&Bs[buf][n0 * SMP + kk];
                b[ni][1] = *(const uint32_t*)&Bs[buf][n0 * SMP + kk + 8];
            }
            #pragma unroll
            for (int mi = 0; mi < 2; mi++)
                #pragma unroll
                for (int ni = 0; ni < 8; ni++)
                    mma16816(acc[mi][ni], a[mi], b[ni]);
        }
        buf ^= 1;
    }

    // epilogue
    #pragma unroll
    for (int mi = 0; mi < 2; mi++) {
        int row = mBase + warpM + mi * 16 + (lane >> 2);
        #pragma unroll
        for (int ni = 0; ni < 8; ni++) {
            int col = nBase + warpN + ni * 8 + (lane & 3) * 2;
            if (!GUARD || col < N) {
                float bb0 = BIAS ? bias[col]     : 0.f;
                float bb1 = BIAS ? bias[col + 1] : 0.f;
                *(float2*)(C + (size_t)row * N + col) =
                    make_float2(acc[mi][ni][0] + bb0, acc[mi][ni][1] + bb1);
                *(float2*)(C + (size_t)(row + 8) * N + col) =
                    make_float2(acc[mi][ni][2] + bb0, acc[mi][ni][3] + bb1);
            }
        }
    }
}

// ---------------------------------------------------------------------------
// Persistent recurrence (unchanged from R2)
// ---------------------------------------------------------------------------
__global__ __launch_bounds__(256, 1)
void rnn_layer_persist(const float* __restrict__ Hinit,
                       const float* __restrict__ W,
                       const float* __restrict__ P,
                       const float* __restrict__ bias,
                       float* __restrict__ Hout)
{
    extern __shared__ float sm[];
    float* Ws = sm;                 // [KS][68]
    float* Hs = sm + KS * 68;       // [BA][132]

    const int t  = threadIdx.x;
    const int ks = blockIdx.x & 7;
    const int cg = blockIdx.x >> 3;

    #pragma unroll
    for (int i = 0; i < 8; i++) {
        int idx = t + i * 256;
        int c = idx >> 5, f = idx & 31;
        float4 v = *(const float4*)(W + (size_t)(cg * NC + c) * HID + ks * KS + 4 * f);
        Ws[(4 * f + 0) * 68 + c] = v.x;
        Ws[(4 * f + 1) * 68 + c] = v.y;
        Ws[(4 * f + 2) * 68 + c] = v.z;
        Ws[(4 * f + 3) * 68 + c] = v.w;
    }

    const int tx = t & 15, ty = t >> 4;
    const int c0 = tx * 4, b0 = ty * 4;

    for (int step = 0; step < SQ; step++) {
        const float* Hprev = (step == 0) ? Hinit : (Hout + (size_t)(step - 1) * BH);

        #pragma unroll
        for (int i = 0; i < 8; i++) {
            int idx = t + i * 256;
            int b = idx >> 5, f = idx & 31;
            float4 v = *(const float4*)(Hprev + (size_t)b * HID + ks * KS + 4 * f);
            *(float4*)(Hs + b * 132 + 4 * f) = v;
        }
        __syncthreads();

        float acc[4][4];
        #pragma unroll
        for (int i = 0; i < 4; i++)
            #pragma unroll
            for (int j = 0; j < 4; j++) acc[i][j] = 0.f;

        #pragma unroll 4
        for (int kk = 0; kk < KS; kk += 4) {
            float4 wv[4], hv[4];
            #pragma unroll
            for (int u = 0; u < 4; u++) wv[u] = *(const float4*)(Ws + (kk + u) * 68 + c0);
            #pragma unroll
            for (int i = 0; i < 4; i++) hv[i] = *(const float4*)(Hs + (b0 + i) * 132 + kk);
            #pragma unroll
            for (int i = 0; i < 4; i++) {
                const float h0v = hv[i].x, h1v = hv[i].y, h2v = hv[i].z, h3v = hv[i].w;
                #pragma unroll
                for (int j = 0; j < 4; j++) {
                    float* a = &acc[i][j];
                    *a += h0v * ((const float*)&wv[0])[j];
                    *a += h1v * ((const float*)&wv[1])[j];
                    *a += h2v * ((const float*)&wv[2])[j];
                    *a += h3v * ((const float*)&wv[3])[j];
                }
            }
        }

        float* pp = g_part + (size_t)ks * BA * HID + (size_t)cg * NC;
        #pragma unroll
        for (int i = 0; i < 4; i++)
            *(float4*)(pp + (size_t)(b0 + i) * HID + c0) =
                make_float4(acc[i][0], acc[i][1], acc[i][2], acc[i][3]);
        __threadfence();
        gbar();

        const float* Pt = P + (size_t)step * BH;
        float*       Ht = Hout + (size_t)step * BH;
        int base = blockIdx.x * 512;
        #pragma unroll
        for (int r = 0; r < 2; r++) {
            int o = base + r * 256 + t;
            int c = o & (HID - 1);
            float s = 0.f;
            #pragma unroll
            for (int k2 = 0; k2 < KSLICES; k2++)
                s += g_part[(size_t)k2 * BA * HID + o];
            Ht[o] = tanhf(s + Pt[o] + bias[c]);
        }
        __threadfence();
        gbar();
    }
}

__global__ void write_hidden(const float* __restrict__ h0, const float* __restrict__ h1,
                             float* __restrict__ dst)
{
    int i = blockIdx.x * 256 + threadIdx.x;
    if (i < BH) {
        dst[i]      = h0[i];
        dst[BH + i] = h1[i];
    }
}

extern "C" void kernel_launch(void* const* d_in, const int* in_sizes, int n_in,
                              void* d_out, int out_size)
{
    const int*   inputs = (const int*)  d_in[0];
    const float* hidden = (const float*)d_in[1];
    const float* emb    = (const float*)d_in[2];
    const float* W0     = (const float*)d_in[3];
    const float* Wh0    = (const float*)d_in[4];
    const float* b0     = (const float*)d_in[5];
    const float* W1     = (const float*)d_in[6];
    const float* Wh1    = (const float*)d_in[7];
    const float* b1     = (const float*)d_in[8];
    const float* Wd     = (const float*)d_in[9];
    const float* bd     = (const float*)d_in[10];
    float* out = (float*)d_out;

    float *P0, *H0, *P1, *H1;
    cudaGetSymbolAddress((void**)&P0, g_P0);
    cudaGetSymbolAddress((void**)&H0, g_H0);
    cudaGetSymbolAddress((void**)&P1, g_P1);
    cudaGetSymbolAddress((void**)&H1, g_H1);
    __nv_bfloat16 *A3, *W03, *W13, *Wd3;
    cudaGetSymbolAddress((void**)&A3,  g_A3);
    cudaGetSymbolAddress((void**)&W03, g_W03);
    cudaGetSymbolAddress((void**)&W13, g_W13);
    cudaGetSymbolAddress((void**)&Wd3, g_Wd3);

    static bool attr_set = false;
    const int smem_bytes = (KS * 68 + BA * 132) * 4;
    if (!attr_set) {
        cudaFuncSetAttribute(rnn_layer_persist,
                             cudaFuncAttributeMaxDynamicSharedMemorySize, smem_bytes);
        attr_set = true;
    }

    const int PK = HID / 4;                  // pack elems per row
    // pack weights (B-order)
    pack_split<false, false><<<(HID  * PK + 255) / 256, 256>>>(W0, nullptr, W03, HID);
    pack_split<false, false><<<(HID  * PK + 255) / 256, 256>>>(W1, nullptr, W13, HID);
    pack_split<false, false><<<(VOC  * PK + 255) / 256, 256>>>(Wd, nullptr, Wd3, VOC);

    // K1: P0 = emb[inputs] @ W0^T  (A packed w/ gather)
    pack_split<true, true><<<(MROWS * PK + 255) / 256, 256>>>(emb, inputs, A3, MROWS);
    gemm_bf16<false, false><<<dim3(MROWS / 128, HID / 128), 256>>>(A3, W03, nullptr, P0, HID);

    // layer 0 recurrence
    rnn_layer_persist<<<NCTA, 256, smem_bytes>>>(hidden, Wh0, P0, b0, H0);

    // K3: P1 = H0 @ W1^T
    pack_split<false, true><<<(MROWS * PK + 255) / 256, 256>>>(H0, nullptr, A3, MROWS);
    gemm_bf16<false, false><<<dim3(MROWS / 128, HID / 128), 256>>>(A3, W13, nullptr, P1, HID);

    // layer 1 recurrence
    rnn_layer_persist<<<NCTA, 256, smem_bytes>>>(hidden + BH, Wh1, P1, b1, H1);

    // decoder: logits = H1 @ Wd^T + bd
    pack_split<false, true><<<(MROWS * PK + 255) / 256, 256>>>(H1, nullptr, A3, MROWS);
    gemm_bf16<true, true><<<dim3(MROWS / 128, (VOC + 127) / 128), 256>>>(A3, Wd3, bd, out, VOC);

    // hidden_final
    if (out_size >= MROWS * VOC + 2 * BH)
        write_hidden<<<(BH + 255) / 256, 256>>>(
            H0 + (size_t)(SQ - 1) * BH, H1 + (size_t)(SQ - 1) * BH,
            out + (size_t)MROWS * VOC);
}

// round 8
// speedup vs baseline: 2.0915x; 1.0381x over previous
#include <cuda_runtime.h>
#include <cuda_bf16.h>
#include <stdint.h>
#include <math.h>

#define SQ   64
#define BA   64
#define HID  1024
#define EMBD 1024
#define VOC  10000
#define BH   (BA*HID)
#define MROWS (SQ*BA)   // 4096
#define K3   (3*HID)    // 3072 split-bf16 K

#define NCTA 128
#define RKS  384        // k3 per slice (3072/8)
#define RPAD 392        // padded smem row stride (halves)

// ---- scratch (device globals) ----
__device__ float g_P0[MROWS*HID];
__device__ float g_P1[MROWS*HID];
__device__ float g_part[8*BA*HID];
__device__ float g_Hlast0[BH];
__device__ float g_Hlast1[BH];

__device__ __nv_bfloat16 g_A3  [MROWS*K3];      // packed A for K1 (emb gather)
__device__ __nv_bfloat16 g_W03 [HID*K3];        // packed weights (B-order hi|lo|hi)
__device__ __nv_bfloat16 g_W13 [HID*K3];
__device__ __nv_bfloat16 g_Wd3 [VOC*K3];
__device__ __nv_bfloat16 g_Wh03[HID*K3];
__device__ __nv_bfloat16 g_Wh13[HID*K3];
__device__ __nv_bfloat16 g_Hp0 [(SQ+1)*BA*K3];  // packed hidden chain, layer0 (A-order)
__device__ __nv_bfloat16 g_Hp1 [(SQ+1)*BA*K3];

__device__ volatile unsigned g_gen;
__device__ unsigned g_cnt;

__device__ __forceinline__ void gbar()
{
    __syncthreads();
    if (threadIdx.x == 0) {
        __threadfence();
        unsigned my = g_gen;
        unsigned a = atomicAdd(&g_cnt, 1);
        if (a == NCTA - 1) {
            atomicExch(&g_cnt, 0);
            __threadfence();
            g_gen = my + 1;
        } else {
            while (g_gen == my) { }
        }
        __threadfence();
    }
    __syncthreads();
}

// ---------------------------------------------------------------------------
// Split-pack: fp32 [R,HID] -> bf16 [R,3*HID].
// A-order (AORD=1): [hi|hi|lo].  B-order (AORD=0): [hi|lo|hi].
// ---------------------------------------------------------------------------
template<bool GATHER, bool AORD>
__global__ __launch_bounds__(256)
void pack_split(const float* __restrict__ src, const int* __restrict__ idx,
                __nv_bfloat16* __restrict__ dst, int R)
{
    long i = (long)blockIdx.x * 256 + threadIdx.x;
    if (i >= (long)R * (HID / 4)) return;
    int r  = (int)(i / (HID / 4));
    int k4 = (int)(i % (HID / 4)) * 4;
    const float* row = GATHER ? (src + (size_t)idx[r] * HID)
                              : (src + (size_t)r * HID);
    float4 v = *(const float4*)(row + k4);

    __nv_bfloat16 h[4], l[4];
    float f[4] = {v.x, v.y, v.z, v.w};
    #pragma unroll
    for (int j = 0; j < 4; j++) {
        h[j] = __float2bfloat16(f[j]);
        l[j] = __float2bfloat16(f[j] - __bfloat162float(h[j]));
    }
    __nv_bfloat16* d = dst + (size_t)r * K3;
    *(uint2*)(d + k4)                        = *(uint2*)h;
    *(uint2*)(d + (AORD ? HID : 2*HID) + k4) = *(uint2*)h;
    *(uint2*)(d + (AORD ? 2*HID : HID) + k4) = *(uint2*)l;
}

__device__ __forceinline__ void mma16816(float* c, const uint32_t* a, const uint32_t* b)
{
    asm volatile(
        "mma.sync.aligned.m16n8k16.row.col.f32.bf16.bf16.f32 "
        "{%0,%1,%2,%3}, {%4,%5,%6,%7}, {%8,%9}, {%0,%1,%2,%3};"
        : "+f"(c[0]), "+f"(c[1]), "+f"(c[2]), "+f"(c[3])
        : "r"(a[0]), "r"(a[1]), "r"(a[2]), "r"(a[3]), "r"(b[0]), "r"(b[1]));
}

// ---------------------------------------------------------------------------
// bf16 tensor-core GEMM (unchanged from R7): C = A[M,K3] @ B[N,K3]^T (+bias)
// ---------------------------------------------------------------------------
#define SMP 40

template<bool BIAS, bool GUARD>
__global__ __launch_bounds__(256, 2)
void gemm_bf16(const __nv_bfloat16* __restrict__ A, const __nv_bfloat16* __restrict__ B,
               const float* __restrict__ bias, float* __restrict__ C, int N)
{
    __shared__ __nv_bfloat16 As[2][128 * SMP];
    __shared__ __nv_bfloat16 Bs[2][128 * SMP];

    const int t    = threadIdx.x;
    const int warp = t >> 5, lane = t & 31;
    const int mBase = blockIdx.x * 128;
    const int nBase = blockIdx.y * 128;
    const int warpM = (warp >> 1) * 32;
    const int warpN = (warp & 1) * 64;

    const int lr = t >> 1;
    const int lk = (t & 1) * 16;

    const __nv_bfloat16* Ag = A + (size_t)(mBase + lr) * K3 + lk;
    int gn = nBase + lr;
    bool bvalid = true;
    if (GUARD && gn >= N) { bvalid = false; gn = N - 1; }
    const __nv_bfloat16* Bg = B + (size_t)gn * K3 + lk;

    uint4 av0 = *(const uint4*)(Ag);
    uint4 av1 = *(const uint4*)(Ag + 8);
    uint4 bv0 = make_uint4(0,0,0,0), bv1 = make_uint4(0,0,0,0);
    if (!GUARD || bvalid) { bv0 = *(const uint4*)(Bg); bv1 = *(const uint4*)(Bg + 8); }

    float acc[2][8][4];
    #pragma unroll
    for (int mi = 0; mi < 2; mi++)
        #pragma unroll
        for (int ni = 0; ni < 8; ni++)
            #pragma unroll
            for (int j = 0; j < 4; j++) acc[mi][ni][j] = 0.f;

    int buf = 0;
    for (int kt = 0; kt < K3; kt += 32) {
        *(uint4*)&As[buf][lr * SMP + lk]     = av0;
        *(uint4*)&As[buf][lr * SMP + lk + 8] = av1;
        *(uint4*)&Bs[buf][lr * SMP + lk]     = bv0;
        *(uint4*)&Bs[buf][lr * SMP + lk + 8] = bv1;
        __syncthreads();

        if (kt + 32 < K3) {
            av0 = *(const uint4*)(Ag + kt + 32);
            av1 = *(const uint4*)(Ag + kt + 40);
            if (!GUARD || bvalid) {
                bv0 = *(const uint4*)(Bg + kt + 32);
                bv1 = *(const uint4*)(Bg + kt + 40);
            }
        }

        #pragma unroll
        for (int ks = 0; ks < 2; ks++) {
            const int kk = ks * 16 + (lane & 3) * 2;
            uint32_t a[2][4], b[8][2];
            #pragma unroll
            for (int mi = 0; mi < 2; mi++) {
                int r0 = warpM + mi * 16 + (lane >> 2);
                a[mi][0] = *(const uint32_t*)&As[buf][ r0      * SMP + kk];
                a[mi][1] = *(const uint32_t*)&As[buf][(r0 + 8) * SMP + kk];
                a[mi][2] = *(const uint32_t*)&As[buf][ r0      * SMP + kk + 8];
                a[mi][3] = *(const uint32_t*)&As[buf][(r0 + 8) * SMP + kk + 8];
            }
            #pragma unroll
            for (int ni = 0; ni < 8; ni++) {
                int n0 = warpN + ni * 8 + (lane >> 2);
                b[ni][0] = *(const uint32_t*)&Bs[buf][n0 * SMP + kk];
                b[ni][1] = *(const uint32_t*)&Bs[buf][n0 * SMP + kk + 8];
            }
            #pragma unroll
            for (int mi = 0; mi < 2; mi++)
                #pragma unroll
                for (int ni = 0; ni < 8; ni++)
                    mma16816(acc[mi][ni], a[mi], b[ni]);
        }
        buf ^= 1;
    }

    #pragma unroll
    for (int mi = 0; mi < 2; mi++) {
        int row = mBase + warpM + mi * 16 + (lane >> 2);
        #pragma unroll
        for (int ni = 0; ni < 8; ni++) {
            int col = nBase + warpN + ni * 8 + (lane & 3) * 2;
            if (!GUARD || col < N) {
                float bb0 = BIAS ? bias[col]     : 0.f;
                float bb1 = BIAS ? bias[col + 1] : 0.f;
                *(float2*)(C + (size_t)row * N + col) =
                    make_float2(acc[mi][ni][0] + bb0, acc[mi][ni][1] + bb1);
                *(float2*)(C + (size_t)(row + 8) * N + col) =
                    make_float2(acc[mi][ni][2] + bb0, acc[mi][ni][3] + bb1);
            }
        }
    }
}

// ---------------------------------------------------------------------------
// Tensor-core persistent recurrence. 128 CTAs = 8 k-slices x 16 col-groups.
// Packed Wh slice (64 cols x 384 k3) resident in smem. Per step:
//   mma split-bf16 partials -> gbar -> reduce+tanh -> write PACKED H (+fp32 last)
// Hpack layout: [(SQ+1)][64][3072]; slot 0 = initial hidden (pre-packed).
// ---------------------------------------------------------------------------
__global__ __launch_bounds__(256, 1)
void rnn_layer_mma(const __nv_bfloat16* __restrict__ Wp,
                   const float* __restrict__ P,
                   const float* __restrict__ bias,
                   __nv_bfloat16* __restrict__ Hpack,
                   float* __restrict__ Hlast)
{
    extern __shared__ __nv_bfloat16 smh[];
    __nv_bfloat16* Bs = smh;                 // [64][RPAD]
    __nv_bfloat16* As = smh + 64 * RPAD;     // [64][RPAD]

    const int t    = threadIdx.x;
    const int ks   = blockIdx.x & 7;
    const int cg   = blockIdx.x >> 3;
    const int warp = t >> 5, lane = t & 31;
    const int mt   = warp & 3;       // m16 tile (batch rows)
    const int nh   = warp >> 2;      // n half (32 cols)

    // resident weight slice: Bs[c][k] = Wp[cg*64+c][ks*RKS+k]
    for (int i = t; i < 64 * 48; i += 256) {
        int c = i / 48, f = i % 48;
        uint4 v = *(const uint4*)(Wp + (size_t)(cg * 64 + c) * K3 + ks * RKS + f * 8);
        *(uint4*)(Bs + c * RPAD + f * 8) = v;
    }

    const int arow = mt * 16 + (lane >> 2);
    const int kq   = (lane & 3) * 2;

    for (int step = 0; step < SQ; step++) {
        const __nv_bfloat16* Ain = Hpack + (size_t)step * (BA * K3) + ks * RKS;
        for (int i = t; i < 64 * 48; i += 256) {
            int b = i / 48, f = i % 48;
            uint4 v = *(const uint4*)(Ain + (size_t)b * K3 + f * 8);
            *(uint4*)(As + b * RPAD + f * 8) = v;
        }
        __syncthreads();

        float acc[4][4];
        #pragma unroll
        for (int nt = 0; nt < 4; nt++)
            #pragma unroll
            for (int j = 0; j < 4; j++) acc[nt][j] = 0.f;

        #pragma unroll 2
        for (int k = 0; k < RKS; k += 16) {
            uint32_t a[4];
            a[0] = *(const uint32_t*)(As + (size_t) arow      * RPAD + k + kq);
            a[1] = *(const uint32_t*)(As + (size_t)(arow + 8) * RPAD + k + kq);
            a[2] = *(const uint32_t*)(As + (size_t) arow      * RPAD + k + kq + 8);
            a[3] = *(const uint32_t*)(As + (size_t)(arow + 8) * RPAD + k + kq + 8);
            #pragma unroll
            for (int nt = 0; nt < 4; nt++) {
                int c = nh * 32 + nt * 8 + (lane >> 2);
                uint32_t b[2];
                b[0] = *(const uint32_t*)(Bs + (size_t)c * RPAD + k + kq);
                b[1] = *(const uint32_t*)(Bs + (size_t)c * RPAD + k + kq + 8);
                mma16816(acc[nt], a, b);
            }
        }

        // partials: g_part[ks][b][global col]
        {
            float* pp = g_part + (size_t)ks * BA * HID + (size_t)cg * 64;
            int r = lane >> 2, cq = (lane & 3) * 2;
            #pragma unroll
            for (int nt = 0; nt < 4; nt++) {
                int c = nh * 32 + nt * 8 + cq;
                *(float2*)(pp + (size_t)(mt * 16 + r)     * HID + c) = make_float2(acc[nt][0], acc[nt][1]);
                *(float2*)(pp + (size_t)(mt * 16 + r + 8) * HID + c) = make_float2(acc[nt][2], acc[nt][3]);
            }
        }
        __threadfence();
        gbar();

        // reduce + tanh + emit packed next-step H
        __nv_bfloat16* Hout = Hpack + (size_t)(step + 1) * (BA * K3);
        const float* Pt = P + (size_t)step * BH;
        int base = blockIdx.x * 512;
        #pragma unroll
        for (int r2 = 0; r2 < 2; r2++) {
            int o = base + r2 * 256 + t;
            int b = o >> 10, c = o & 1023;
            float s = 0.f;
            #pragma unroll
            for (int k2 = 0; k2 < 8; k2++)
                s += g_part[(size_t)k2 * BA * HID + o];
            float h = tanhf(s + Pt[o] + bias[c]);
            __nv_bfloat16 hi = __float2bfloat16(h);
            __nv_bfloat16 lo = __float2bfloat16(h - __bfloat162float(hi));
            __nv_bfloat16* dr = Hout + (size_t)b * K3;
            dr[c]           = hi;
            dr[HID + c]     = hi;
            dr[2 * HID + c] = lo;
            if (step == SQ - 1) Hlast[o] = h;
        }
        __threadfence();
        gbar();
    }
}

__global__ void write_hidden(const float* __restrict__ h0, const float* __restrict__ h1,
                             float* __restrict__ dst)
{
    int i = blockIdx.x * 256 + threadIdx.x;
    if (i < BH) {
        dst[i]      = h0[i];
        dst[BH + i] = h1[i];
    }
}

extern "C" void kernel_launch(void* const* d_in, const int* in_sizes, int n_in,
                              void* d_out, int out_size)
{
    const int*   inputs = (const int*)  d_in[0];
    const float* hidden = (const float*)d_in[1];
    const float* emb    = (const float*)d_in[2];
    const float* W0     = (const float*)d_in[3];
    const float* Wh0    = (const float*)d_in[4];
    const float* b0     = (const float*)d_in[5];
    const float* W1     = (const float*)d_in[6];
    const float* Wh1    = (const float*)d_in[7];
    const float* b1     = (const float*)d_in[8];
    const float* Wd     = (const float*)d_in[9];
    const float* bd     = (const float*)d_in[10];
    float* out = (float*)d_out;

    float *P0, *P1, *Hl0, *Hl1;
    cudaGetSymbolAddress((void**)&P0,  g_P0);
    cudaGetSymbolAddress((void**)&P1,  g_P1);
    cudaGetSymbolAddress((void**)&Hl0, g_Hlast0);
    cudaGetSymbolAddress((void**)&Hl1, g_Hlast1);
    __nv_bfloat16 *A3, *W03, *W13, *Wd3, *Wh03, *Wh13, *Hp0, *Hp1;
    cudaGetSymbolAddress((void**)&A3,   g_A3);
    cudaGetSymbolAddress((void**)&W03,  g_W03);
    cudaGetSymbolAddress((void**)&W13,  g_W13);
    cudaGetSymbolAddress((void**)&Wd3,  g_Wd3);
    cudaGetSymbolAddress((void**)&Wh03, g_Wh03);
    cudaGetSymbolAddress((void**)&Wh13, g_Wh13);
    cudaGetSymbolAddress((void**)&Hp0,  g_Hp0);
    cudaGetSymbolAddress((void**)&Hp1,  g_Hp1);

    static bool attr_set = false;
    const int rec_smem = 2 * 64 * RPAD * 2;   // 100352 B
    if (!attr_set) {
        cudaFuncSetAttribute(rnn_layer_mma,
                             cudaFuncAttributeMaxDynamicSharedMemorySize, rec_smem);
        attr_set = true;
    }

    const int PK = HID / 4;

    // pack weights (B-order)
    pack_split<false, false><<<(HID * PK + 255) / 256, 256>>>(W0,  nullptr, W03,  HID);
    pack_split<false, false><<<(HID * PK + 255) / 256, 256>>>(W1,  nullptr, W13,  HID);
    pack_split<false, false><<<(VOC * PK + 255) / 256, 256>>>(Wd,  nullptr, Wd3,  VOC);
    pack_split<false, false><<<(HID * PK + 255) / 256, 256>>>(Wh0, nullptr, Wh03, HID);
    pack_split<false, false><<<(HID * PK + 255) / 256, 256>>>(Wh1, nullptr, Wh13, HID);

    // initial hidden -> packed slot 0 (A-order)
    pack_split<false, true><<<(BA * PK + 255) / 256, 256>>>(hidden,      nullptr, Hp0, BA);
    pack_split<false, true><<<(BA * PK + 255) / 256, 256>>>(hidden + BH, nullptr, Hp1, BA);

    // K1: P0 = emb[inputs] @ W0^T
    pack_split<true, true><<<(MROWS * PK + 255) / 256, 256>>>(emb, inputs, A3, MROWS);
    gemm_bf16<false, false><<<dim3(MROWS / 128, HID / 128), 256>>>(A3, W03, nullptr, P0, HID);

    // layer 0 recurrence (tensor-core, emits packed H chain)
    rnn_layer_mma<<<NCTA, 256, rec_smem>>>(Wh03, P0, b0, Hp0, Hl0);

    // K3: P1 = H0 @ W1^T  (A = packed chain slots 1..SQ)
    gemm_bf16<false, false><<<dim3(MROWS / 128, HID / 128), 256>>>(Hp0 + (size_t)BA * K3, W13, nullptr, P1, HID);

    // layer 1 recurrence
    rnn_layer_mma<<<NCTA, 256, rec_smem>>>(Wh13, P1, b1, Hp1, Hl1);

    // decoder: logits = H1 @ Wd^T + bd
    gemm_bf16<true, true><<<dim3(MROWS / 128, (VOC + 127) / 128), 256>>>(
        Hp1 + (size_t)BA * K3, Wd3, bd, out, VOC);

    // hidden_final
    if (out_size >= MROWS * VOC + 2 * BH)
        write_hidden<<<(BH + 255) / 256, 256>>>(Hl0, Hl1, out + (size_t)MROWS * VOC);
}

// round 12
// speedup vs baseline: 2.1815x; 1.0430x over previous
#include <cuda_runtime.h>
#include <cuda_bf16.h>
#include <stdint.h>
#include <math.h>

#define SQ   64
#define BA   64
#define HID  1024
#define EMBD 1024
#define VOC  10000
#define BH   (BA*HID)
#define MROWS (SQ*BA)   // 4096
#define K3   (3*HID)    // 3072 split-bf16 K

#define NCTA 128
#define RKS  384        // k3 per slice (3072/8)
#define RPAD 392        // padded smem row stride (halves)

// ---- scratch (device globals) ----
__device__ float g_P0[MROWS*HID];
__device__ float g_P1[MROWS*HID];
__device__ float g_part[8*BA*HID];
__device__ float g_Hlast0[BH];
__device__ float g_Hlast1[BH];

__device__ __nv_bfloat16 g_A3  [MROWS*K3];      // packed A for K1 (emb gather)
__device__ __nv_bfloat16 g_W03 [HID*K3];        // packed weights (B-order hi|lo|hi)
__device__ __nv_bfloat16 g_W13 [HID*K3];
__device__ __nv_bfloat16 g_Wd3 [VOC*K3];
__device__ __nv_bfloat16 g_Wh03[HID*K3];
__device__ __nv_bfloat16 g_Wh13[HID*K3];
__device__ __nv_bfloat16 g_Hp0 [(SQ+1)*BA*K3];  // packed hidden chain, layer0 (A-order)
__device__ __nv_bfloat16 g_Hp1 [(SQ+1)*BA*K3];

// ---- hierarchical grid barrier state (monotone counters, never reset) ----
__device__ unsigned g_leaf[8 * 32];   // 8 leaf counters, 128B apart
__device__ unsigned g_root;
__device__ volatile unsigned g_gen;

// Hierarchical sense-reversing barrier for NCTA=128 CTAs.
// Arrival: 16 same-address atomics per leaf (8 leaves in parallel) + 8 root
// atomics => ~650cyc drain vs ~3500cyc for a single 128-way counter.
// Counters are modular (wrap-safe), so no reset stores and no reset races.
__device__ __forceinline__ void gbar()
{
    __syncthreads();
    if (threadIdx.x == 0) {
        __threadfence();                       // release prior global stores
        unsigned my = g_gen;
        const int leaf = (blockIdx.x & 7) * 32;
        if ((atomicAdd(&g_leaf[leaf], 1u) & 15u) == 15u) {
            if ((atomicAdd(&g_root, 1u) & 7u) == 7u) {
                __threadfence();
                g_gen = my + 1;
            }
        }
        while (g_gen == my) { }
        __threadfence();                       // acquire released stores
    }
    __syncthreads();
}

// ---------------------------------------------------------------------------
// Split-pack: fp32 [R,HID] -> bf16 [R,3*HID].
// A-order (AORD=1): [hi|hi|lo].  B-order (AORD=0): [hi|lo|hi].
// ---------------------------------------------------------------------------
template<bool GATHER, bool AORD>
__global__ __launch_bounds__(256)
void pack_split(const float* __restrict__ src, const int* __restrict__ idx,
                __nv_bfloat16* __restrict__ dst, int R)
{
    long i = (long)blockIdx.x * 256 + threadIdx.x;
    if (i >= (long)R * (HID / 4)) return;
    int r  = (int)(i / (HID / 4));
    int k4 = (int)(i % (HID / 4)) * 4;
    const float* row = GATHER ? (src + (size_t)idx[r] * HID)
                              : (src + (size_t)r * HID);
    float4 v = *(const float4*)(row + k4);

    __nv_bfloat16 h[4], l[4];
    float f[4] = {v.x, v.y, v.z, v.w};
    #pragma unroll
    for (int j = 0; j < 4; j++) {
        h[j] = __float2bfloat16(f[j]);
        l[j] = __float2bfloat16(f[j] - __bfloat162float(h[j]));
    }
    __nv_bfloat16* d = dst + (size_t)r * K3;
    *(uint2*)(d + k4)                        = *(uint2*)h;
    *(uint2*)(d + (AORD ? HID : 2*HID) + k4) = *(uint2*)h;
    *(uint2*)(d + (AORD ? 2*HID : HID) + k4) = *(uint2*)l;
}

__device__ __forceinline__ void mma16816(float* c, const uint32_t* a, const uint32_t* b)
{
    asm volatile(
        "mma.sync.aligned.m16n8k16.row.col.f32.bf16.bf16.f32 "
        "{%0,%1,%2,%3}, {%4,%5,%6,%7}, {%8,%9}, {%0,%1,%2,%3};"
        : "+f"(c[0]), "+f"(c[1]), "+f"(c[2]), "+f"(c[3])
        : "r"(a[0]), "r"(a[1]), "r"(a[2]), "r"(a[3]), "r"(b[0]), "r"(b[1]));
}

// ---------------------------------------------------------------------------
// bf16 tensor-core GEMM (mma.sync): C = A[M,K3] @ B[N,K3]^T (+bias)
// CTA 128x128, K-tile 32, 256 threads (8 warps: 4m x 2n), double-buffered.
// ---------------------------------------------------------------------------
#define SMP 40

template<bool BIAS, bool GUARD>
__global__ __launch_bounds__(256, 2)
void gemm_bf16(const __nv_bfloat16* __restrict__ A, const __nv_bfloat16* __restrict__ B,
               const float* __restrict__ bias, float* __restrict__ C, int N)
{
    __shared__ __nv_bfloat16 As[2][128 * SMP];
    __shared__ __nv_bfloat16 Bs[2][128 * SMP];

    const int t    = threadIdx.x;
    const int warp = t >> 5, lane = t & 31;
    const int mBase = blockIdx.x * 128;
    const int nBase = blockIdx.y * 128;
    const int warpM = (warp >> 1) * 32;
    const int warpN = (warp & 1) * 64;

    const int lr = t >> 1;
    const int lk = (t & 1) * 16;

    const __nv_bfloat16* Ag = A + (size_t)(mBase + lr) * K3 + lk;
    int gn = nBase + lr;
    bool bvalid = true;
    if (GUARD && gn >= N) { bvalid = false; gn = N - 1; }
    const __nv_bfloat16* Bg = B + (size_t)gn * K3 + lk;

    uint4 av0 = *(const uint4*)(Ag);
    uint4 av1 = *(const uint4*)(Ag + 8);
    uint4 bv0 = make_uint4(0,0,0,0), bv1 = make_uint4(0,0,0,0);
    if (!GUARD || bvalid) { bv0 = *(const uint4*)(Bg); bv1 = *(const uint4*)(Bg + 8); }

    float acc[2][8][4];
    #pragma unroll
    for (int mi = 0; mi < 2; mi++)
        #pragma unroll
        for (int ni = 0; ni < 8; ni++)
            #pragma unroll
            for (int j = 0; j < 4; j++) acc[mi][ni][j] = 0.f;

    int buf = 0;
    for (int kt = 0; kt < K3; kt += 32) {
        *(uint4*)&As[buf][lr * SMP + lk]     = av0;
        *(uint4*)&As[buf][lr * SMP + lk + 8] = av1;
        *(uint4*)&Bs[buf][lr * SMP + lk]     = bv0;
        *(uint4*)&Bs[buf][lr * SMP + lk + 8] = bv1;
        __syncthreads();

        if (kt + 32 < K3) {
            av0 = *(const uint4*)(Ag + kt + 32);
            av1 = *(const uint4*)(Ag + kt + 40);
            if (!GUARD || bvalid) {
                bv0 = *(const uint4*)(Bg + kt + 32);
                bv1 = *(const uint4*)(Bg + kt + 40);
            }
        }

        #pragma unroll
        for (int ks = 0; ks < 2; ks++) {
            const int kk = ks * 16 + (lane & 3) * 2;
            uint32_t a[2][4], b[8][2];
            #pragma unroll
            for (int mi = 0; mi < 2; mi++) {
                int r0 = warpM + mi * 16 + (lane >> 2);
                a[mi][0] = *(const uint32_t*)&As[buf][ r0      * SMP + kk];
                a[mi][1] = *(const uint32_t*)&As[buf][(r0 + 8) * SMP + kk];
                a[mi][2] = *(const uint32_t*)&As[buf][ r0      * SMP + kk + 8];
                a[mi][3] = *(const uint32_t*)&As[buf][(r0 + 8) * SMP + kk + 8];
            }
            #pragma unroll
            for (int ni = 0; ni < 8; ni++) {
                int n0 = warpN + ni * 8 + (lane >> 2);
                b[ni][0] = *(const uint32_t*)&Bs[buf][n0 * SMP + kk];
                b[ni][1] = *(const uint32_t*)&Bs[buf][n0 * SMP + kk + 8];
            }
            #pragma unroll
            for (int mi = 0; mi < 2; mi++)
                #pragma unroll
                for (int ni = 0; ni < 8; ni++)
                    mma16816(acc[mi][ni], a[mi], b[ni]);
        }
        buf ^= 1;
    }

    #pragma unroll
    for (int mi = 0; mi < 2; mi++) {
        int row = mBase + warpM + mi * 16 + (lane >> 2);
        #pragma unroll
        for (int ni = 0; ni < 8; ni++) {
            int col = nBase + warpN + ni * 8 + (lane & 3) * 2;
            if (!GUARD || col < N) {
                float bb0 = BIAS ? bias[col]     : 0.f;
                float bb1 = BIAS ? bias[col + 1] : 0.f;
                *(float2*)(C + (size_t)row * N + col) =
                    make_float2(acc[mi][ni][0] + bb0, acc[mi][ni][1] + bb1);
                *(float2*)(C + (size_t)(row + 8) * N + col) =
                    make_float2(acc[mi][ni][2] + bb0, acc[mi][ni][3] + bb1);
            }
        }
    }
}

// ---------------------------------------------------------------------------
// Tensor-core persistent recurrence. 128 CTAs = 8 k-slices x 16 col-groups.
// Packed Wh slice resident in smem. Fences live inside gbar().
// ---------------------------------------------------------------------------
__global__ __launch_bounds__(256, 1)
void rnn_layer_mma(const __nv_bfloat16* __restrict__ Wp,
                   const float* __restrict__ P,
                   const float* __restrict__ bias,
                   __nv_bfloat16* __restrict__ Hpack,
                   float* __restrict__ Hlast)
{
    extern __shared__ __nv_bfloat16 smh[];
    __nv_bfloat16* Bs = smh;                 // [64][RPAD]
    __nv_bfloat16* As = smh + 64 * RPAD;     // [64][RPAD]

    const int t    = threadIdx.x;
    const int ks   = blockIdx.x & 7;
    const int cg   = blockIdx.x >> 3;
    const int warp = t >> 5, lane = t & 31;
    const int mt   = warp & 3;
    const int nh   = warp >> 2;

    for (int i = t; i < 64 * 48; i += 256) {
        int c = i / 48, f = i % 48;
        uint4 v = *(const uint4*)(Wp + (size_t)(cg * 64 + c) * K3 + ks * RKS + f * 8);
        *(uint4*)(Bs + c * RPAD + f * 8) = v;
    }

    const int arow = mt * 16 + (lane >> 2);
    const int kq   = (lane & 3) * 2;

    for (int step = 0; step < SQ; step++) {
        const __nv_bfloat16* Ain = Hpack + (size_t)step * (BA * K3) + ks * RKS;
        for (int i = t; i < 64 * 48; i += 256) {
            int b = i / 48, f = i % 48;
            uint4 v = *(const uint4*)(Ain + (size_t)b * K3 + f * 8);
            *(uint4*)(As + b * RPAD + f * 8) = v;
        }
        __syncthreads();

        float acc[4][4];
        #pragma unroll
        for (int nt = 0; nt < 4; nt++)
            #pragma unroll
            for (int j = 0; j < 4; j++) acc[nt][j] = 0.f;

        #pragma unroll 2
        for (int k = 0; k < RKS; k += 16) {
            uint32_t a[4];
            a[0] = *(const uint32_t*)(As + (size_t) arow      * RPAD + k + kq);
            a[1] = *(const uint32_t*)(As + (size_t)(arow + 8) * RPAD + k + kq);
            a[2] = *(const uint32_t*)(As + (size_t) arow      * RPAD + k + kq + 8);
            a[3] = *(const uint32_t*)(As + (size_t)(arow + 8) * RPAD + k + kq + 8);
            #pragma unroll
            for (int nt = 0; nt < 4; nt++) {
                int c = nh * 32 + nt * 8 + (lane >> 2);
                uint32_t b[2];
                b[0] = *(const uint32_t*)(Bs + (size_t)c * RPAD + k + kq);
                b[1] = *(const uint32_t*)(Bs + (size_t)c * RPAD + k + kq + 8);
                mma16816(acc[nt], a, b);
            }
        }

        {
            float* pp = g_part + (size_t)ks * BA * HID + (size_t)cg * 64;
            int r = lane >> 2, cq = (lane & 3) * 2;
            #pragma unroll
            for (int nt = 0; nt < 4; nt++) {
                int c = nh * 32 + nt * 8 + cq;
                *(float2*)(pp + (size_t)(mt * 16 + r)     * HID + c) = make_float2(acc[nt][0], acc[nt][1]);
                *(float2*)(pp + (size_t)(mt * 16 + r + 8) * HID + c) = make_float2(acc[nt][2], acc[nt][3]);
            }
        }
        gbar();

        __nv_bfloat16* Hout = Hpack + (size_t)(step + 1) * (BA * K3);
        const float* Pt = P + (size_t)step * BH;
        int base = blockIdx.x * 512;
        #pragma unroll
        for (int r2 = 0; r2 < 2; r2++) {
            int o = base + r2 * 256 + t;
            int b = o >> 10, c = o & 1023;
            float s = 0.f;
            #pragma unroll
            for (int k2 = 0; k2 < 8; k2++)
                s += g_part[(size_t)k2 * BA * HID + o];
            float h = tanhf(s + Pt[o] + bias[c]);
            __nv_bfloat16 hi = __float2bfloat16(h);
            __nv_bfloat16 lo = __float2bfloat16(h - __bfloat162float(hi));
            __nv_bfloat16* dr = Hout + (size_t)b * K3;
            dr[c]           = hi;
            dr[HID + c]     = hi;
            dr[2 * HID + c] = lo;
            if (step == SQ - 1) Hlast[o] = h;
        }
        gbar();
    }
}

__global__ void write_hidden(const float* __restrict__ h0, const float* __restrict__ h1,
                             float* __restrict__ dst)
{
    int i = blockIdx.x * 256 + threadIdx.x;
    if (i < BH) {
        dst[i]      = h0[i];
        dst[BH + i] = h1[i];
    }
}

extern "C" void kernel_launch(void* const* d_in, const int* in_sizes, int n_in,
                              void* d_out, int out_size)
{
    const int*   inputs = (const int*)  d_in[0];
    const float* hidden = (const float*)d_in[1];
    const float* emb    = (const float*)d_in[2];
    const float* W0     = (const float*)d_in[3];
    const float* Wh0    = (const float*)d_in[4];
    const float* b0     = (const float*)d_in[5];
    const float* W1     = (const float*)d_in[6];
    const float* Wh1    = (const float*)d_in[7];
    const float* b1     = (const float*)d_in[8];
    const float* Wd     = (const float*)d_in[9];
    const float* bd     = (const float*)d_in[10];
    float* out = (float*)d_out;

    float *P0, *P1, *Hl0, *Hl1;
    cudaGetSymbolAddress((void**)&P0,  g_P0);
    cudaGetSymbolAddress((void**)&P1,  g_P1);
    cudaGetSymbolAddress((void**)&Hl0, g_Hlast0);
    cudaGetSymbolAddress((void**)&Hl1, g_Hlast1);
    __nv_bfloat16 *A3, *W03, *W13, *Wd3, *Wh03, *Wh13, *Hp0, *Hp1;
    cudaGetSymbolAddress((void**)&A3,   g_A3);
    cudaGetSymbolAddress((void**)&W03,  g_W03);
    cudaGetSymbolAddress((void**)&W13,  g_W13);
    cudaGetSymbolAddress((void**)&Wd3,  g_Wd3);
    cudaGetSymbolAddress((void**)&Wh03, g_Wh03);
    cudaGetSymbolAddress((void**)&Wh13, g_Wh13);
    cudaGetSymbolAddress((void**)&Hp0,  g_Hp0);
    cudaGetSymbolAddress((void**)&Hp1,  g_Hp1);

    static bool attr_set = false;
    const int rec_smem = 2 * 64 * RPAD * 2;   // 100352 B
    if (!attr_set) {
        cudaFuncSetAttribute(rnn_layer_mma,
                             cudaFuncAttributeMaxDynamicSharedMemorySize, rec_smem);
        attr_set = true;
    }

    const int PK = HID / 4;

    // pack weights (B-order)
    pack_split<false, false><<<(HID * PK + 255) / 256, 256>>>(W0,  nullptr, W03,  HID);
    pack_split<false, false><<<(HID * PK + 255) / 256, 256>>>(W1,  nullptr, W13,  HID);
    pack_split<false, false><<<(VOC * PK + 255) / 256, 256>>>(Wd,  nullptr, Wd3,  VOC);
    pack_split<false, false><<<(HID * PK + 255) / 256, 256>>>(Wh0, nullptr, Wh03, HID);
    pack_split<false, false><<<(HID * PK + 255) / 256, 256>>>(Wh1, nullptr, Wh13, HID);

    // initial hidden -> packed slot 0 (A-order)
    pack_split<false, true><<<(BA * PK + 255) / 256, 256>>>(hidden,      nullptr, Hp0, BA);
    pack_split<false, true><<<(BA * PK + 255) / 256, 256>>>(hidden + BH, nullptr, Hp1, BA);

    // K1: P0 = emb[inputs] @ W0^T
    pack_split<true, true><<<(MROWS * PK + 255) / 256, 256>>>(emb, inputs, A3, MROWS);
    gemm_bf16<false, false><<<dim3(MROWS / 128, HID / 128), 256>>>(A3, W03, nullptr, P0, HID);

    // layer 0 recurrence
    rnn_layer_mma<<<NCTA, 256, rec_smem>>>(Wh03, P0, b0, Hp0, Hl0);

    // K3: P1 = H0 @ W1^T
    gemm_bf16<false, false><<<dim3(MROWS / 128, HID / 128), 256>>>(
        Hp0 + (size_t)BA * K3, W13, nullptr, P1, HID);

    // layer 1 recurrence
    rnn_layer_mma<<<NCTA, 256, rec_smem>>>(Wh13, P1, b1, Hp1, Hl1);

    // decoder: logits = H1 @ Wd^T + bd
    gemm_bf16<true, true><<<dim3(MROWS / 128, (VOC + 127) / 128), 256>>>(
        Hp1 + (size_t)BA * K3, Wd3, bd, out, VOC);

    // hidden_final
    if (out_size >= MROWS * VOC + 2 * BH)
        write_hidden<<<(BH + 255) / 256, 256>>>(Hl0, Hl1, out + (size_t)MROWS * VOC);
}

// round 13
// speedup vs baseline: 2.4321x; 1.1149x over previous
#include <cuda_runtime.h>
#include <cuda_bf16.h>
#include <stdint.h>
#include <math.h>

#define SQ   64
#define BA   64
#define HID  1024
#define EMBD 1024
#define VOC  10000
#define BH   (BA*HID)
#define MROWS (SQ*BA)   // 4096
#define K3   (3*HID)    // 3072 split-bf16 K

#define NCTA 128
#define RKS  384        // layer0 k3 per slice (3072/8)
#define RKS2 768        // layer1 k6144 per slice (6144/8)
#define RPAD 392        // padded smem row stride (halves)

// ---- scratch (device globals) ----
__device__ float g_P0[MROWS*HID];
__device__ float g_part0[8*BA*HID];
__device__ float g_part1[8*BA*HID];
__device__ float g_Hlast0[BH];
__device__ float g_Hlast1[BH];

__device__ __nv_bfloat16 g_A3  [MROWS*K3];      // packed A for K1 (emb gather)
__device__ __nv_bfloat16 g_W03 [HID*K3];        // packed weights (B-order hi|lo|hi)
__device__ __nv_bfloat16 g_W13 [HID*K3];
__device__ __nv_bfloat16 g_Wd3 [VOC*K3];
__device__ __nv_bfloat16 g_Wh03[HID*K3];
__device__ __nv_bfloat16 g_Wh13[HID*K3];
__device__ __nv_bfloat16 g_Hp0 [(SQ+1)*BA*K3];  // packed hidden chains (A-order)
__device__ __nv_bfloat16 g_Hp1 [(SQ+1)*BA*K3];

// ---- hierarchical grid barrier (monotone counters, wrap-safe) ----
__device__ unsigned g_leaf[8 * 32];
__device__ unsigned g_root;
__device__ volatile unsigned g_gen;

__device__ __forceinline__ void gbar()
{
    __syncthreads();
    if (threadIdx.x == 0) {
        __threadfence();
        unsigned my = g_gen;
        const int leaf = (blockIdx.x & 7) * 32;
        if ((atomicAdd(&g_leaf[leaf], 1u) & 15u) == 15u) {
            if ((atomicAdd(&g_root, 1u) & 7u) == 7u) {
                __threadfence();
                g_gen = my + 1;
            }
        }
        while (g_gen == my) { }
        __threadfence();
    }
    __syncthreads();
}

// ---------------------------------------------------------------------------
// Split-pack: fp32 [R,HID] -> bf16 [R,3*HID].
// A-order (AORD=1): [hi|hi|lo].  B-order (AORD=0): [hi|lo|hi].
// ---------------------------------------------------------------------------
template<bool GATHER, bool AORD>
__global__ __launch_bounds__(256)
void pack_split(const float* __restrict__ src, const int* __restrict__ idx,
                __nv_bfloat16* __restrict__ dst, int R)
{
    long i = (long)blockIdx.x * 256 + threadIdx.x;
    if (i >= (long)R * (HID / 4)) return;
    int r  = (int)(i / (HID / 4));
    int k4 = (int)(i % (HID / 4)) * 4;
    const float* row = GATHER ? (src + (size_t)idx[r] * HID)
                              : (src + (size_t)r * HID);
    float4 v = *(const float4*)(row + k4);

    __nv_bfloat16 h[4], l[4];
    float f[4] = {v.x, v.y, v.z, v.w};
    #pragma unroll
    for (int j = 0; j < 4; j++) {
        h[j] = __float2bfloat16(f[j]);
        l[j] = __float2bfloat16(f[j] - __bfloat162float(h[j]));
    }
    __nv_bfloat16* d = dst + (size_t)r * K3;
    *(uint2*)(d + k4)                        = *(uint2*)h;
    *(uint2*)(d + (AORD ? HID : 2*HID) + k4) = *(uint2*)h;
    *(uint2*)(d + (AORD ? 2*HID : HID) + k4) = *(uint2*)l;
}

__device__ __forceinline__ void mma16816(float* c, const uint32_t* a, const uint32_t* b)
{
    asm volatile(
        "mma.sync.aligned.m16n8k16.row.col.f32.bf16.bf16.f32 "
        "{%0,%1,%2,%3}, {%4,%5,%6,%7}, {%8,%9}, {%0,%1,%2,%3};"
        : "+f"(c[0]), "+f"(c[1]), "+f"(c[2]), "+f"(c[3])
        : "r"(a[0]), "r"(a[1]), "r"(a[2]), "r"(a[3]), "r"(b[0]), "r"(b[1]));
}

// ---------------------------------------------------------------------------
// bf16 tensor-core GEMM (mma.sync): C = A[M,K3] @ B[N,K3]^T (+bias)
// ---------------------------------------------------------------------------
#define SMP 40

template<bool BIAS, bool GUARD>
__global__ __launch_bounds__(256, 2)
void gemm_bf16(const __nv_bfloat16* __restrict__ A, const __nv_bfloat16* __restrict__ B,
               const float* __restrict__ bias, float* __restrict__ C, int N)
{
    __shared__ __nv_bfloat16 As[2][128 * SMP];
    __shared__ __nv_bfloat16 Bs[2][128 * SMP];

    const int t    = threadIdx.x;
    const int warp = t >> 5, lane = t & 31;
    const int mBase = blockIdx.x * 128;
    const int nBase = blockIdx.y * 128;
    const int warpM = (warp >> 1) * 32;
    const int warpN = (warp & 1) * 64;

    const int lr = t >> 1;
    const int lk = (t & 1) * 16;

    const __nv_bfloat16* Ag = A + (size_t)(mBase + lr) * K3 + lk;
    int gn = nBase + lr;
    bool bvalid = true;
    if (GUARD && gn >= N) { bvalid = false; gn = N - 1; }
    const __nv_bfloat16* Bg = B + (size_t)gn * K3 + lk;

    uint4 av0 = *(const uint4*)(Ag);
    uint4 av1 = *(const uint4*)(Ag + 8);
    uint4 bv0 = make_uint4(0,0,0,0), bv1 = make_uint4(0,0,0,0);
    if (!GUARD || bvalid) { bv0 = *(const uint4*)(Bg); bv1 = *(const uint4*)(Bg + 8); }

    float acc[2][8][4];
    #pragma unroll
    for (int mi = 0; mi < 2; mi++)
        #pragma unroll
        for (int ni = 0; ni < 8; ni++)
            #pragma unroll
            for (int j = 0; j < 4; j++) acc[mi][ni][j] = 0.f;

    int buf = 0;
    for (int kt = 0; kt < K3; kt += 32) {
        *(uint4*)&As[buf][lr * SMP + lk]     = av0;
        *(uint4*)&As[buf][lr * SMP + lk + 8] = av1;
        *(uint4*)&Bs[buf][lr * SMP + lk]     = bv0;
        *(uint4*)&Bs[buf][lr * SMP + lk + 8] = bv1;
        __syncthreads();

        if (kt + 32 < K3) {
            av0 = *(const uint4*)(Ag + kt + 32);
            av1 = *(const uint4*)(Ag + kt + 40);
            if (!GUARD || bvalid) {
                bv0 = *(const uint4*)(Bg + kt + 32);
                bv1 = *(const uint4*)(Bg + kt + 40);
            }
        }

        #pragma unroll
        for (int ks = 0; ks < 2; ks++) {
            const int kk = ks * 16 + (lane & 3) * 2;
            uint32_t a[2][4], b[8][2];
            #pragma unroll
            for (int mi = 0; mi < 2; mi++) {
                int r0 = warpM + mi * 16 + (lane >> 2);
                a[mi][0] = *(const uint32_t*)&As[buf][ r0      * SMP + kk];
                a[mi][1] = *(const uint32_t*)&As[buf][(r0 + 8) * SMP + kk];
                a[mi][2] = *(const uint32_t*)&As[buf][ r0      * SMP + kk + 8];
                a[mi][3] = *(const uint32_t*)&As[buf][(r0 + 8) * SMP + kk + 8];
            }
            #pragma unroll
            for (int ni = 0; ni < 8; ni++) {
                int n0 = warpN + ni * 8 + (lane >> 2);
                b[ni][0] = *(const uint32_t*)&Bs[buf][n0 * SMP + kk];
                b[ni][1] = *(const uint32_t*)&Bs[buf][n0 * SMP + kk + 8];
            }
            #pragma unroll
            for (int mi = 0; mi < 2; mi++)
                #pragma unroll
                for (int ni = 0; ni < 8; ni++)
                    mma16816(acc[mi][ni], a[mi], b[ni]);
        }
        buf ^= 1;
    }

    #pragma unroll
    for (int mi = 0; mi < 2; mi++) {
        int row = mBase + warpM + mi * 16 + (lane >> 2);
        #pragma unroll
        for (int ni = 0; ni < 8; ni++) {
            int col = nBase + warpN + ni * 8 + (lane & 3) * 2;
            if (!GUARD || col < N) {
                float bb0 = BIAS ? bias[col]     : 0.f;
                float bb1 = BIAS ? bias[col + 1] : 0.f;
                *(float2*)(C + (size_t)row * N + col) =
                    make_float2(acc[mi][ni][0] + bb0, acc[mi][ni][1] + bb1);
                *(float2*)(C + (size_t)(row + 8) * N + col) =
                    make_float2(acc[mi][ni][2] + bb0, acc[mi][ni][3] + bb1);
            }
        }
    }
}

// ---------------------------------------------------------------------------
// Fused 2-layer wavefront recurrence. 128 CTAs = 8 k-slices x 16 col-groups.
// Wave w: layer0 step w (if w<SQ) + layer1 step w-1 (if w>=1).
// Layer1 folds P1: h1 = tanh([h0 ; h1prev] @ [W1 ; Wh1]^T + b1), K=6144 packed.
// Resident smem: Wh0 slice (384k), W1/Wh1 slice chunks (2x384k) + As staging.
// ---------------------------------------------------------------------------
__device__ __forceinline__ void mma_block(const __nv_bfloat16* As, const __nv_bfloat16* Bs,
                                          int arow, int kq, int crow, float acc[4][4])
{
    #pragma unroll 2
    for (int k = 0; k < RKS; k += 16) {
        uint32_t a[4];
        a[0] = *(const uint32_t*)(As + (size_t) arow      * RPAD + k + kq);
        a[1] = *(const uint32_t*)(As + (size_t)(arow + 8) * RPAD + k + kq);
        a[2] = *(const uint32_t*)(As + (size_t) arow      * RPAD + k + kq + 8);
        a[3] = *(const uint32_t*)(As + (size_t)(arow + 8) * RPAD + k + kq + 8);
        #pragma unroll
        for (int nt = 0; nt < 4; nt++) {
            int c = crow + nt * 8;
            uint32_t b[2];
            b[0] = *(const uint32_t*)(Bs + (size_t)c * RPAD + k + kq);
            b[1] = *(const uint32_t*)(Bs + (size_t)c * RPAD + k + kq + 8);
            mma16816(acc[nt], a, b);
        }
    }
}

__global__ __launch_bounds__(256, 1)
void rnn_fused(const __nv_bfloat16* __restrict__ Wh0p,
               const __nv_bfloat16* __restrict__ W1p,
               const __nv_bfloat16* __restrict__ Wh1p,
               const float* __restrict__ P0,
               const float* __restrict__ bias0,
               const float* __restrict__ bias1,
               __nv_bfloat16* __restrict__ Hp0,
               __nv_bfloat16* __restrict__ Hp1,
               float* __restrict__ Hl0,
               float* __restrict__ Hl1)
{
    extern __shared__ __nv_bfloat16 smh[];
    __nv_bfloat16* B0s = smh;                    // layer0 weight slice
    __nv_bfloat16* B1a = smh + 64 * RPAD;        // layer1 weight chunk 0
    __nv_bfloat16* B1b = smh + 2 * 64 * RPAD;    // layer1 weight chunk 1
    __nv_bfloat16* As  = smh + 3 * 64 * RPAD;    // activation staging

    const int t    = threadIdx.x;
    const int ks   = blockIdx.x & 7;
    const int cg   = blockIdx.x >> 3;
    const int warp = t >> 5, lane = t & 31;
    const int mt   = warp & 3;
    const int nh   = warp >> 2;

    // resident weight slices
    for (int i = t; i < 64 * 48; i += 256) {
        int c = i / 48, f = i % 48;
        *(uint4*)(B0s + c * RPAD + f * 8) =
            *(const uint4*)(Wh0p + (size_t)(cg * 64 + c) * K3 + ks * RKS + f * 8);
    }
    {
        const __nv_bfloat16* Wsrc = (ks < 4) ? W1p : Wh1p;
        const int colbase = (ks & 3) * RKS2;
        for (int i = t; i < 64 * 48; i += 256) {
            int c = i / 48, f = i % 48;
            *(uint4*)(B1a + c * RPAD + f * 8) =
                *(const uint4*)(Wsrc + (size_t)(cg * 64 + c) * K3 + colbase + f * 8);
            *(uint4*)(B1b + c * RPAD + f * 8) =
                *(const uint4*)(Wsrc + (size_t)(cg * 64 + c) * K3 + colbase + RKS + f * 8);
        }
    }

    const int arow = mt * 16 + (lane >> 2);
    const int kq   = (lane & 3) * 2;
    const int crow = nh * 32 + (lane >> 2);

    for (int w = 0; w <= SQ; w++) {
        float acc0[4][4], acc1[4][4];

        // ---- phase A: layer0 step w ----
        if (w < SQ) {
            const __nv_bfloat16* Ain = Hp0 + (size_t)w * (BA * K3) + ks * RKS;
            __syncthreads();
            for (int i = t; i < 64 * 48; i += 256) {
                int b = i / 48, f = i % 48;
                *(uint4*)(As + b * RPAD + f * 8) = *(const uint4*)(Ain + (size_t)b * K3 + f * 8);
            }
            __syncthreads();

            #pragma unroll
            for (int nt = 0; nt < 4; nt++)
                #pragma unroll
                for (int j = 0; j < 4; j++) acc0[nt][j] = 0.f;
            mma_block(As, B0s, arow, kq, crow, acc0);

            float* pp = g_part0 + (size_t)ks * BA * HID + (size_t)cg * 64;
            int r = lane >> 2, cq = (lane & 3) * 2;
            #pragma unroll
            for (int nt = 0; nt < 4; nt++) {
                int c = nh * 32 + nt * 8 + cq;
                *(float2*)(pp + (size_t)(mt * 16 + r)     * HID + c) = make_float2(acc0[nt][0], acc0[nt][1]);
                *(float2*)(pp + (size_t)(mt * 16 + r + 8) * HID + c) = make_float2(acc0[nt][2], acc0[nt][3]);
            }
        }

        // ---- phase B: layer1 step w-1 (K-concat folds P1) ----
        if (w >= 1) {
            const __nv_bfloat16* src = (ks < 4)
                ? (Hp0 + (size_t)w       * (BA * K3) + ks * RKS2)
                : (Hp1 + (size_t)(w - 1) * (BA * K3) + (ks - 4) * RKS2);

            #pragma unroll
            for (int nt = 0; nt < 4; nt++)
                #pragma unroll
                for (int j = 0; j < 4; j++) acc1[nt][j] = 0.f;

            #pragma unroll
            for (int ch = 0; ch < 2; ch++) {
                __syncthreads();
                for (int i = t; i < 64 * 48; i += 256) {
                    int b = i / 48, f = i % 48;
                    *(uint4*)(As + b * RPAD + f * 8) =
                        *(const uint4*)(src + (size_t)b * K3 + ch * RKS + f * 8);
                }
                __syncthreads();
                mma_block(As, ch ? B1b : B1a, arow, kq, crow, acc1);
            }

            float* pp = g_part1 + (size_t)ks * BA * HID + (size_t)cg * 64;
            int r = lane >> 2, cq = (lane & 3) * 2;
            #pragma unroll
            for (int nt = 0; nt < 4; nt++) {
                int c = nh * 32 + nt * 8 + cq;
                *(float2*)(pp + (size_t)(mt * 16 + r)     * HID + c) = make_float2(acc1[nt][0], acc1[nt][1]);
                *(float2*)(pp + (size_t)(mt * 16 + r + 8) * HID + c) = make_float2(acc1[nt][2], acc1[nt][3]);
            }
        }

        gbar();

        // ---- reduce + tanh + pack ----
        if (w < SQ) {
            __nv_bfloat16* Hout = Hp0 + (size_t)(w + 1) * (BA * K3);
            const float* Pt = P0 + (size_t)w * BH;
            int base = blockIdx.x * 512;
            #pragma unroll
            for (int r2 = 0; r2 < 2; r2++) {
                int o = base + r2 * 256 + t;
                int b = o >> 10, c = o & 1023;
                float s = 0.f;
                #pragma unroll
                for (int k2 = 0; k2 < 8; k2++)
                    s += g_part0[(size_t)k2 * BA * HID + o];
                float h = tanhf(s + Pt[o] + bias0[c]);
                __nv_bfloat16 hi = __float2bfloat16(h);
                __nv_bfloat16 lo = __float2bfloat16(h - __bfloat162float(hi));
                __nv_bfloat16* dr = Hout + (size_t)b * K3;
                dr[c]           = hi;
                dr[HID + c]     = hi;
                dr[2 * HID + c] = lo;
                if (w == SQ - 1) Hl0[o] = h;
            }
        }
        if (w >= 1) {
            __nv_bfloat16* Hout = Hp1 + (size_t)w * (BA * K3);
            int base = blockIdx.x * 512;
            #pragma unroll
            for (int r2 = 0; r2 < 2; r2++) {
                int o = base + r2 * 256 + t;
                int b = o >> 10, c = o & 1023;
                float s = 0.f;
                #pragma unroll
                for (int k2 = 0; k2 < 8; k2++)
                    s += g_part1[(size_t)k2 * BA * HID + o];
                float h = tanhf(s + bias1[c]);
                __nv_bfloat16 hi = __float2bfloat16(h);
                __nv_bfloat16 lo = __float2bfloat16(h - __bfloat162float(hi));
                __nv_bfloat16* dr = Hout + (size_t)b * K3;
                dr[c]           = hi;
                dr[HID + c]     = hi;
                dr[2 * HID + c] = lo;
                if (w == SQ) Hl1[o] = h;
            }
        }
        gbar();
    }
}

__global__ void write_hidden(const float* __restrict__ h0, const float* __restrict__ h1,
                             float* __restrict__ dst)
{
    int i = blockIdx.x * 256 + threadIdx.x;
    if (i < BH) {
        dst[i]      = h0[i];
        dst[BH + i] = h1[i];
    }
}

extern "C" void kernel_launch(void* const* d_in, const int* in_sizes, int n_in,
                              void* d_out, int out_size)
{
    const int*   inputs = (const int*)  d_in[0];
    const float* hidden = (const float*)d_in[1];
    const float* emb    = (const float*)d_in[2];
    const float* W0     = (const float*)d_in[3];
    const float* Wh0    = (const float*)d_in[4];
    const float* b0     = (const float*)d_in[5];
    const float* W1     = (const float*)d_in[6];
    const float* Wh1    = (const float*)d_in[7];
    const float* b1     = (const float*)d_in[8];
    const float* Wd     = (const float*)d_in[9];
    const float* bd     = (const float*)d_in[10];
    float* out = (float*)d_out;

    float *P0, *Hl0, *Hl1;
    cudaGetSymbolAddress((void**)&P0,  g_P0);
    cudaGetSymbolAddress((void**)&Hl0, g_Hlast0);
    cudaGetSymbolAddress((void**)&Hl1, g_Hlast1);
    __nv_bfloat16 *A3, *W03, *W13, *Wd3, *Wh03, *Wh13, *Hp0, *Hp1;
    cudaGetSymbolAddress((void**)&A3,   g_A3);
    cudaGetSymbolAddress((void**)&W03,  g_W03);
    cudaGetSymbolAddress((void**)&W13,  g_W13);
    cudaGetSymbolAddress((void**)&Wd3,  g_Wd3);
    cudaGetSymbolAddress((void**)&Wh03, g_Wh03);
    cudaGetSymbolAddress((void**)&Wh13, g_Wh13);
    cudaGetSymbolAddress((void**)&Hp0,  g_Hp0);
    cudaGetSymbolAddress((void**)&Hp1,  g_Hp1);

    static bool attr_set = false;
    const int rec_smem = 4 * 64 * RPAD * 2;   // 200704 B
    if (!attr_set) {
        cudaFuncSetAttribute(rnn_fused,
                             cudaFuncAttributeMaxDynamicSharedMemorySize, rec_smem);
        attr_set = true;
    }

    const int PK = HID / 4;

    // pack weights (B-order)
    pack_split<false, false><<<(HID * PK + 255) / 256, 256>>>(W0,  nullptr, W03,  HID);
    pack_split<false, false><<<(HID * PK + 255) / 256, 256>>>(W1,  nullptr, W13,  HID);
    pack_split<false, false><<<(VOC * PK + 255) / 256, 256>>>(Wd,  nullptr, Wd3,  VOC);
    pack_split<false, false><<<(HID * PK + 255) / 256, 256>>>(Wh0, nullptr, Wh03, HID);
    pack_split<false, false><<<(HID * PK + 255) / 256, 256>>>(Wh1, nullptr, Wh13, HID);

    // initial hidden -> packed chain slot 0 (A-order)
    pack_split<false, true><<<(BA * PK + 255) / 256, 256>>>(hidden,      nullptr, Hp0, BA);
    pack_split<false, true><<<(BA * PK + 255) / 256, 256>>>(hidden + BH, nullptr, Hp1, BA);

    // K1: P0 = emb[inputs] @ W0^T
    pack_split<true, true><<<(MROWS * PK + 255) / 256, 256>>>(emb, inputs, A3, MROWS);
    gemm_bf16<false, false><<<dim3(MROWS / 128, HID / 128), 256>>>(A3, W03, nullptr, P0, HID);

    // fused 2-layer wavefront recurrence (folds the H0@W1^T GEMM)
    rnn_fused<<<NCTA, 256, rec_smem>>>(Wh03, W13, Wh13, P0, b0, b1, Hp0, Hp1, Hl0, Hl1);

    // decoder: logits = H1 @ Wd^T + bd
    gemm_bf16<true, true><<<dim3(MROWS / 128, (VOC + 127) / 128), 256>>>(
        Hp1 + (size_t)BA * K3, Wd3, bd, out, VOC);

    // hidden_final
    if (out_size >= MROWS * VOC + 2 * BH)
        write_hidden<<<(BH + 255) / 256, 256>>>(Hl0, Hl1, out + (size_t)MROWS * VOC);
}